// round 5
// baseline (speedup 1.0000x reference)
#include <cuda_runtime.h>
#include <cuda_fp16.h>
#include <cstdint>
#include <cstddef>

// AspectAttention round 5: fp16 mma.sync m16n8k16, A staged as fp16 + ldmatrix.x4.
// CTA: 128 rows x 256 cols, 256 thr = 8 warps (2m x 4n), warp tile 64x64.
// W fragment-packed fp16, fully smem-resident (128KB, cp.async once).
// h: LDG.128 f32 -> cvt.f16x2 -> STS.64 into 2 rotating 16KB fp16 slots (KC=64),
// fragments fetched with ldmatrix.x4 (conflict-free via XOR-(row&7)<<4 swizzle).

#define THREADS   256
#define KC        64
#define BOFF      0
#define BBYTES    131072
#define AOFF(s)   (BBYTES + (s) * 16384)      // 128 rows x 128B fp16
#define RP_OFF    (BBYTES + 32768)
#define SMEM_BYTES (RP_OFF + 2048)

__device__ __half g_Wpack[16 * 256 * 16];     // [sg][col][tig][{b0.lo,b0.hi,b1.lo,b1.hi}]

// ---------------- helpers ----------------
__device__ __forceinline__ float tanh_fast(float x) {
    float y; asm("tanh.approx.f32 %0, %1;" : "=f"(y) : "f"(x)); return y;
}
__device__ __forceinline__ uint32_t pack2(float hi, float lo) {
    uint32_t r; asm("cvt.rn.f16x2.f32 %0, %1, %2;" : "=r"(r) : "f"(hi), "f"(lo)); return r;
}
__device__ __forceinline__ void mma_fp16(float (&c)[4],
                                         uint32_t a0, uint32_t a1, uint32_t a2, uint32_t a3,
                                         uint32_t b0, uint32_t b1) {
    asm volatile(
        "mma.sync.aligned.m16n8k16.row.col.f32.f16.f16.f32 "
        "{%0,%1,%2,%3},{%4,%5,%6,%7},{%8,%9},{%0,%1,%2,%3};"
        : "+f"(c[0]), "+f"(c[1]), "+f"(c[2]), "+f"(c[3])
        : "r"(a0), "r"(a1), "r"(a2), "r"(a3), "r"(b0), "r"(b1));
}
__device__ __forceinline__ void ldmatrix4(uint32_t (&d)[4], uint32_t addr) {
    asm volatile("ldmatrix.sync.aligned.m8n8.x4.shared.b16 {%0,%1,%2,%3}, [%4];"
                 : "=r"(d[0]), "=r"(d[1]), "=r"(d[2]), "=r"(d[3]) : "r"(addr));
}
__device__ __forceinline__ void cp_async16(uint32_t sa, const void* g) {
    asm volatile("cp.async.cg.shared.global [%0], [%1], 16;" :: "r"(sa), "l"(g));
}

// ---------------- W pack: fp16 fragment order (identical to R4, proven) --------
__global__ void pack_w_kernel(const float* __restrict__ W) {
    const int s   = blockIdx.x;      // 0..15
    const int col = threadIdx.x;     // 0..255
    #pragma unroll
    for (int t = 0; t < 4; ++t) {
        __half* dst = g_Wpack + ((s * 256 + col) * 4 + t) * 4;
        dst[0] = __float2half_rn(W[(16 * s + 2 * t)     * 256 + col]);
        dst[1] = __float2half_rn(W[(16 * s + 2 * t + 1) * 256 + col]);
        dst[2] = __float2half_rn(W[(16 * s + 2 * t + 8) * 256 + col]);
        dst[3] = __float2half_rn(W[(16 * s + 2 * t + 9) * 256 + col]);
    }
}

// ---------------- main kernel ----------------
__global__ __launch_bounds__(THREADS)
void aspect_attention_kernel(const float* __restrict__ h,
                             const float* __restrict__ bias,
                             float* __restrict__ out) {
    extern __shared__ __align__(16) char dynsmem[];
    const uint32_t smem_u32 = (uint32_t)__cvta_generic_to_shared(dynsmem);

    const int tid  = threadIdx.x;
    const int w    = tid >> 5;
    const int lane = tid & 31;
    const int g    = lane >> 2;
    const int tig  = lane & 3;
    const int wm   = w & 1;        // row block: wm*64
    const int wn   = w >> 1;       // col block: wn*64

    // ldmatrix per-thread constants
    const int arow0    = wm * 64 + (lane & 7) + ((lane >> 3) & 1) * 8;  // + mf*16
    const uint32_t X   = ((uint32_t)(lane & 7)) << 4;
    const uint32_t kL  = ((uint32_t)((lane >> 4) & 1)) * 16;            // + ss*32

    // LDG/STS constants
    const int srow  = tid >> 4;      // + j*16
    const int squad = tid & 15;

    const float* hb = h + (size_t)blockIdx.x * (128 * 256);
    const char* sB = dynsmem + BOFF;

    float acc[4][8][4];
    #pragma unroll
    for (int mf = 0; mf < 4; ++mf)
        #pragma unroll
        for (int nt = 0; nt < 8; ++nt)
            #pragma unroll
            for (int i = 0; i < 4; ++i) acc[mf][nt][i] = 0.0f;

    float4 buf[8];

    #define LDG_CHUNK(c) do {                                                     \
        const float* src_ = hb + (c) * KC;                                        \
        _Pragma("unroll")                                                         \
        for (int j = 0; j < 8; ++j)                                               \
            buf[j] = *(const float4*)(src_ + (srow + j * 16) * 256 + squad * 4);  \
    } while (0)

    #define STS_CHUNK(slot) do {                                                  \
        uint32_t base_ = smem_u32 + AOFF(slot);                                   \
        _Pragma("unroll")                                                         \
        for (int j = 0; j < 8; ++j) {                                             \
            uint32_t b_ = (uint32_t)((srow + j * 16) * 128 + squad * 8);          \
            uint32_t sw_ = b_ ^ ((b_ >> 3) & 0x70);                               \
            uint32_t u0_ = pack2(buf[j].y, buf[j].x);                             \
            uint32_t u1_ = pack2(buf[j].w, buf[j].z);                             \
            asm volatile("st.shared.v2.u32 [%0], {%1,%2};"                        \
                         :: "r"(base_ + sw_), "r"(u0_), "r"(u1_));                \
        }                                                                         \
    } while (0)

    #define COMPUTE(c) do {                                                       \
        uint32_t abase_ = smem_u32 + AOFF((c) & 1);                               \
        _Pragma("unroll")                                                         \
        for (int ss = 0; ss < 4; ++ss) {                                          \
            uint32_t a[4][4];                                                     \
            _Pragma("unroll")                                                     \
            for (int mf = 0; mf < 4; ++mf) {                                      \
                uint32_t b_ = (uint32_t)((arow0 + mf * 16) * 128) + kL + ss * 32; \
                ldmatrix4(a[mf], abase_ + (b_ ^ X));                              \
            }                                                                     \
            const int sg_ = (c) * 4 + ss;                                         \
            _Pragma("unroll")                                                     \
            for (int nt = 0; nt < 8; ++nt) {                                      \
                int col_ = wn * 64 + nt * 8 + g;                                  \
                uint2 bb_ = *(const uint2*)(sB + ((sg_ * 256 + col_) * 4 + tig) * 8); \
                _Pragma("unroll")                                                 \
                for (int mf = 0; mf < 4; ++mf)                                    \
                    mma_fp16(acc[mf][nt], a[mf][0], a[mf][1], a[mf][2], a[mf][3], \
                             bb_.x, bb_.y);                                       \
            }                                                                     \
        }                                                                         \
    } while (0)

    // ---- prologue: B resident via cp.async; chunk0 LDG->STS; chunk1 LDG ----
    {
        const char* bsrc = (const char*)g_Wpack;
        #pragma unroll
        for (int it = 0; it < 32; ++it) {
            int i_ = it * THREADS + tid;
            cp_async16(smem_u32 + BOFF + i_ * 16, bsrc + i_ * 16);
        }
        asm volatile("cp.async.commit_group;");
    }
    LDG_CHUNK(0);
    STS_CHUNK(0);
    LDG_CHUNK(1);
    asm volatile("cp.async.wait_group 0;");
    __syncthreads();

    // ---- main loop (4 chunks of KC=64) ----
    COMPUTE(0);
    __syncthreads();
    STS_CHUNK(1);          // buf = chunk 1
    LDG_CHUNK(2);
    __syncthreads();

    COMPUTE(1);
    __syncthreads();
    STS_CHUNK(0);          // buf = chunk 2
    LDG_CHUNK(3);
    __syncthreads();

    COMPUTE(2);
    __syncthreads();
    STS_CHUNK(1);          // buf = chunk 3
    __syncthreads();

    COMPUTE(3);

    // ---- epilogue phase 1: e = exp(tanh(s + bias)); intra-warp column sums ----
    float psum[16];
    #pragma unroll
    for (int j = 0; j < 16; ++j) psum[j] = 0.0f;

    #pragma unroll
    for (int mf = 0; mf < 4; ++mf)
        #pragma unroll
        for (int hi = 0; hi < 2; ++hi) {
            int row = wm * 64 + mf * 16 + hi * 8 + g;
            const float* brow = bias + (row & 63) * 256 + wn * 64 + 2 * tig;
            #pragma unroll
            for (int nt = 0; nt < 8; ++nt) {
                float2 bb = *(const float2*)(brow + nt * 8);
                float e0 = __expf(tanh_fast(acc[mf][nt][2 * hi + 0] + bb.x));
                float e1 = __expf(tanh_fast(acc[mf][nt][2 * hi + 1] + bb.y));
                acc[mf][nt][2 * hi + 0] = e0;
                acc[mf][nt][2 * hi + 1] = e1;
                psum[nt * 2 + 0] += e0;
                psum[nt * 2 + 1] += e1;
            }
        }

    #pragma unroll
    for (int j = 0; j < 16; ++j) {
        psum[j] += __shfl_xor_sync(0xffffffffu, psum[j], 4);
        psum[j] += __shfl_xor_sync(0xffffffffu, psum[j], 8);
        psum[j] += __shfl_xor_sync(0xffffffffu, psum[j], 16);
        psum[j] = 1.0f / psum[j];            // inv(colsum)
    }

    // ---- phase 2: out[row] = sum_col e * inv * h ----
    float part[8];
    #pragma unroll
    for (int mf = 0; mf < 4; ++mf)
        #pragma unroll
        for (int hi = 0; hi < 2; ++hi) {
            int row = wm * 64 + mf * 16 + hi * 8 + g;
            const float* hrow = hb + row * 256 + wn * 64 + 2 * tig;
            float p = 0.0f;
            #pragma unroll
            for (int nt = 0; nt < 8; ++nt) {
                float2 hh = *(const float2*)(hrow + nt * 8);
                p += acc[mf][nt][2 * hi + 0] * psum[nt * 2 + 0] * hh.x;
                p += acc[mf][nt][2 * hi + 1] * psum[nt * 2 + 1] * hh.y;
            }
            part[mf * 2 + hi] = p;
        }

    #pragma unroll
    for (int s = 0; s < 8; ++s) {
        part[s] += __shfl_xor_sync(0xffffffffu, part[s], 1);
        part[s] += __shfl_xor_sync(0xffffffffu, part[s], 2);
    }
    float* rowpart = (float*)(dynsmem + RP_OFF);
    __syncthreads();
    if (tig == 0) {
        #pragma unroll
        for (int s = 0; s < 8; ++s) {
            int row = wm * 64 + (s >> 1) * 16 + (s & 1) * 8 + g;
            rowpart[wn * 128 + row] = part[s];
        }
    }
    __syncthreads();

    if (tid < 128) {
        float v = rowpart[tid] + rowpart[128 + tid] + rowpart[256 + tid] + rowpart[384 + tid];
        out[(size_t)blockIdx.x * 128 + tid] = v;
    }
}

extern "C" void kernel_launch(void* const* d_in, const int* in_sizes, int n_in,
                              void* d_out, int out_size) {
    const float* h    = (const float*)d_in[0];  // [4096, 64, 256]
    const float* W    = (const float*)d_in[1];  // [256, 256]
    const float* bias = (const float*)d_in[2];  // [64, 256]
    float* out = (float*)d_out;                 // [4096, 64]

    pack_w_kernel<<<16, 256>>>(W);

    cudaFuncSetAttribute(aspect_attention_kernel,
                         cudaFuncAttributeMaxDynamicSharedMemorySize, SMEM_BYTES);
    aspect_attention_kernel<<<2048, THREADS, SMEM_BYTES>>>(h, bias, out);
}